// round 1
// baseline (speedup 1.0000x reference)
#include <cuda_runtime.h>
#include <cstdint>
#include <cstddef>

// ---------------- problem constants (fixed by setup_inputs) ----------------
#define NCAV     2
#define WIN      8
#define HH       256            // H
#define WW       256            // W
#define NWY      (HH/WIN)       // 32
#define NWX      (WW/WIN)       // 32
#define NWIN     (NWY*NWX)      // 1024
#define BWIN     (NCAV*NWIN)    // 2048 windows
#define NTOK     64             // tokens per window
#define CH       256            // channels
#define NHEAD    8
#define HD       32             // head dim
#define MROWS    (BWIN*NTOK)    // 131072
#define SCALE_Q  0.17677669529663687f   // 32^-0.5
#define PI_F     3.14159274101257324f

// ---------------- scratch (device globals: no runtime allocation) ----------
__device__ float g_q [BWIN*NHEAD*NTOK*HD];   // (b,h,n,d)
__device__ float g_k [BWIN*NHEAD*NTOK*HD];
__device__ float g_v [BWIN*NHEAD*NTOK*HD];
__device__ float g_ao[MROWS*CH];             // attention output, (b*64+n, h*32+d)
__device__ float g_wqkv[CH*768];
__device__ float g_bqkv[768];
__device__ int   g_egoidx[BWIN];

// ---------------- helpers ----------------
__device__ __forceinline__ uint32_t f2t(float f) {
    uint32_t r;
    asm("cvt.rna.tf32.f32 %0, %1;\n" : "=r"(r) : "f"(f));
    return r;
}

__device__ __forceinline__ void mma_tf32(float c[4], const uint32_t a[4], const uint32_t b[2]) {
    asm volatile(
        "mma.sync.aligned.m16n8k8.row.col.f32.tf32.tf32.f32 "
        "{%0,%1,%2,%3},{%4,%5,%6,%7},{%8,%9},{%0,%1,%2,%3};\n"
        : "+f"(c[0]), "+f"(c[1]), "+f"(c[2]), "+f"(c[3])
        : "r"(a[0]), "r"(a[1]), "r"(a[2]), "r"(a[3]), "r"(b[0]), "r"(b[1]));
}

// ---------------- kernel 1: pack Wq|Wkv and biases ----------------
__global__ void pack_kernel(const float* __restrict__ Wq, const float* __restrict__ bq,
                            const float* __restrict__ Wkv, const float* __restrict__ bkv) {
    int t = blockIdx.x * blockDim.x + threadIdx.x;      // 768 blocks * 256 = 196608 = 256*768
    int k = t / 768, j = t % 768;
    g_wqkv[t] = (j < CH) ? Wq[k*CH + j] : Wkv[k*512 + (j - CH)];
    if (t < 768) g_bqkv[t] = (t < CH) ? bq[t] : bkv[t - CH];
}

// ---------------- kernel 2: ego bias bin index ----------------
__global__ void ego_kernel(const float* __restrict__ A) {
    __shared__ float rx[BWIN], ry[BWIN];
    __shared__ float red[256];
    int tid = threadIdx.x;
    float ex[NCAV], ey[NCAV];
#pragma unroll
    for (int c = 0; c < NCAV; c++) {
        ex[c] = A[c*6 + 0] * 128.0f + A[c*6 + 1] * 128.0f + A[c*6 + 2];
        ey[c] = A[c*6 + 3] * 128.0f + A[c*6 + 4] * 128.0f + A[c*6 + 5];
    }
    float lmax = 0.0f;
    for (int i = tid; i < BWIN; i += 256) {
        int cav = i >> 10, wi = i & 1023;
        int gy = wi >> 5, gx = wi & 31;
        float cx = gx * (float)WIN + WIN * 0.5f;
        float cy = gy * (float)WIN + WIN * 0.5f;
        float rxx = cx - ex[cav], ryy = cy - ey[cav];
        rx[i] = rxx; ry[i] = ryy;
        float d = sqrtf(rxx * rxx + ryy * ryy);
        lmax = fmaxf(lmax, d);
    }
    red[tid] = lmax;
    __syncthreads();
    for (int s = 128; s > 0; s >>= 1) {
        if (tid < s) red[tid] = fmaxf(red[tid], red[tid + s]);
        __syncthreads();
    }
    float maxd = red[0] + 1e-6f;
    for (int i = tid; i < BWIN; i += 256) {
        float rxx = rx[i], ryy = ry[i];
        float d = sqrtf(rxx * rxx + ryy * ryy);
        float ratio = d / maxd;
        int db = (int)(ratio * 3.0f);
        float ang = atan2f(ryy, rxx);
        int ab = (int)((ang + PI_F) / (2.0f * PI_F) * 3.0f);
        g_egoidx[i] = db * 4 + ab;
    }
}

// ---------------- kernel 3/5: TF32 GEMM, C[M,N] = A[M,256] @ B[256,N] + bias ----
// mode 0: A = x, B = g_wqkv (ldb=768); epilogue scatters into g_q/g_k/g_v with q*scale
// mode 1: A = g_ao, B = Wp (ldb=256); epilogue writes d_out
__global__ __launch_bounds__(256) void gemm_tf32(
    const float* __restrict__ A_in, const float* __restrict__ B_in,
    const float* __restrict__ bias_in, int ldb, int mode, float* __restrict__ out)
{
    const float* __restrict__ Ap    = (mode == 0) ? A_in : g_ao;
    const float* __restrict__ Bp    = (mode == 0) ? g_wqkv : B_in;
    const float* __restrict__ biasp = (mode == 0) ? g_bqkv : bias_in;

    const int bm0 = blockIdx.y * 128;
    const int bn0 = blockIdx.x * 128;

    __shared__ uint32_t As[16][132];   // [k][m], pad 4
    __shared__ uint32_t Bs[16][132];   // [k][n], pad 4

    int tid  = threadIdx.x;
    int warp = tid >> 5, lane = tid & 31;
    int wm = (warp & 1) * 64;     // warp M offset
    int wn = (warp >> 1) * 32;    // warp N offset
    int gid = lane >> 2, tig = lane & 3;

    float acc[4][4][4];
#pragma unroll
    for (int i = 0; i < 4; i++)
#pragma unroll
        for (int j = 0; j < 4; j++)
#pragma unroll
            for (int e = 0; e < 4; e++) acc[i][j][e] = 0.0f;

    for (int k0 = 0; k0 < 256; k0 += 16) {
        // A tile 128x16 -> As[k][m] (transposed store)
#pragma unroll
        for (int i = 0; i < 2; i++) {
            int v = tid + i * 256;
            int row = v >> 2, c4 = v & 3;
            float4 x = *(const float4*)(Ap + (size_t)(bm0 + row) * 256 + k0 + c4 * 4);
            As[c4*4 + 0][row] = f2t(x.x);
            As[c4*4 + 1][row] = f2t(x.y);
            As[c4*4 + 2][row] = f2t(x.z);
            As[c4*4 + 3][row] = f2t(x.w);
        }
        // B tile 16x128 -> Bs[k][n]
#pragma unroll
        for (int i = 0; i < 2; i++) {
            int v = tid + i * 256;
            int kr = v >> 5, c4 = v & 31;
            float4 x = *(const float4*)(Bp + (size_t)(k0 + kr) * ldb + bn0 + c4 * 4);
            uint4 t;
            t.x = f2t(x.x); t.y = f2t(x.y); t.z = f2t(x.z); t.w = f2t(x.w);
            *(uint4*)&Bs[kr][c4 * 4] = t;
        }
        __syncthreads();

#pragma unroll
        for (int ks = 0; ks < 16; ks += 8) {
            uint32_t af[4][4], bf[4][2];
#pragma unroll
            for (int mt = 0; mt < 4; mt++) {
                int m = wm + mt * 16 + gid;
                af[mt][0] = As[ks + tig    ][m];
                af[mt][1] = As[ks + tig    ][m + 8];
                af[mt][2] = As[ks + tig + 4][m];
                af[mt][3] = As[ks + tig + 4][m + 8];
            }
#pragma unroll
            for (int nt = 0; nt < 4; nt++) {
                int n = wn + nt * 8 + gid;
                bf[nt][0] = Bs[ks + tig    ][n];
                bf[nt][1] = Bs[ks + tig + 4][n];
            }
#pragma unroll
            for (int mt = 0; mt < 4; mt++)
#pragma unroll
                for (int nt = 0; nt < 4; nt++)
                    mma_tf32(acc[mt][nt], af[mt], bf[nt]);
        }
        __syncthreads();
    }

    // epilogue
#pragma unroll
    for (int mt = 0; mt < 4; mt++) {
#pragma unroll
        for (int nt = 0; nt < 4; nt++) {
#pragma unroll
            for (int e = 0; e < 4; e++) {
                int r = gid + ((e >= 2) ? 8 : 0);
                int col = 2 * tig + (e & 1);
                int m = bm0 + wm + mt * 16 + r;
                int n = bn0 + wn + nt * 8 + col;
                float val = acc[mt][nt][e] + biasp[n];
                if (mode == 0) {
                    int part = n >> 8;          // 0=q,1=k,2=v
                    int cc = n & 255;
                    int head = cc >> 5, d = cc & 31;
                    int b = m >> 6, tok = m & 63;
                    if (part == 0) val *= SCALE_Q;
                    float* dst = (part == 0) ? g_q : ((part == 1) ? g_k : g_v);
                    dst[(((size_t)(b * NHEAD + head)) * NTOK + tok) * HD + d] = val;
                } else {
                    out[(size_t)m * CH + n] = val;
                }
            }
        }
    }
}

// ---------------- kernel 4: per (window,head) attention ----------------
__global__ __launch_bounds__(128) void attn_kernel(
    const float* __restrict__ rel_table, const float* __restrict__ ego_table,
    const float* __restrict__ wvec)
{
    __shared__ float sq [NTOK][36];    // q rows, pad to 36 (16B-aligned rows)
    __shared__ float skT[HD][NTOK];    // k transposed [d][m]
    __shared__ float sv [NTOK][HD];
    __shared__ float sS [NTOK][68];    // scores/probs, pad 68
    __shared__ float srel[225];

    int bh = blockIdx.x;               // 0..16383
    int b = bh >> 3, head = bh & 7;
    int tid = threadIdx.x;
    int tr = tid >> 3;                 // 0..15
    int tc = tid & 7;                  // 0..7

    size_t base = (size_t)bh * (NTOK * HD);

    // load tiles
#pragma unroll
    for (int i = 0; i < 4; i++) {
        int v = tid + i * 128;         // 0..511
        int row = v >> 3, c4 = v & 7;
        float4 qd = *(const float4*)(g_q + base + row * HD + c4 * 4);
        *(float4*)&sq[row][c4 * 4] = qd;
        float4 kd = *(const float4*)(g_k + base + row * HD + c4 * 4);
        skT[c4*4 + 0][row] = kd.x;
        skT[c4*4 + 1][row] = kd.y;
        skT[c4*4 + 2][row] = kd.z;
        skT[c4*4 + 3][row] = kd.w;
        float4 vd = *(const float4*)(g_v + base + row * HD + c4 * 4);
        *(float4*)&sv[row][c4 * 4] = vd;
    }
    for (int i = tid; i < 225; i += 128) srel[i] = rel_table[i * NHEAD + head];
    __syncthreads();

    // S = (q*scale) @ k^T  (scale already folded into q)
    float acc[4][8];
#pragma unroll
    for (int i = 0; i < 4; i++)
#pragma unroll
        for (int m = 0; m < 8; m++) acc[i][m] = 0.0f;

#pragma unroll
    for (int d4 = 0; d4 < 8; d4++) {
        float4 qv[4];
#pragma unroll
        for (int i = 0; i < 4; i++) qv[i] = *(float4*)&sq[tr + 16 * i][d4 * 4];
#pragma unroll
        for (int j = 0; j < 4; j++) {
            int d = d4 * 4 + j;
            float4 ka = *(float4*)&skT[d][tc * 8];
            float4 kb = *(float4*)&skT[d][tc * 8 + 4];
            float kk0 = ka.x, kk1 = ka.y, kk2 = ka.z, kk3 = ka.w;
            float kk4 = kb.x, kk5 = kb.y, kk6 = kb.z, kk7 = kb.w;
#pragma unroll
            for (int i = 0; i < 4; i++) {
                float qq = (j == 0) ? qv[i].x : (j == 1) ? qv[i].y : (j == 2) ? qv[i].z : qv[i].w;
                acc[i][0] = fmaf(qq, kk0, acc[i][0]);
                acc[i][1] = fmaf(qq, kk1, acc[i][1]);
                acc[i][2] = fmaf(qq, kk2, acc[i][2]);
                acc[i][3] = fmaf(qq, kk3, acc[i][3]);
                acc[i][4] = fmaf(qq, kk4, acc[i][4]);
                acc[i][5] = fmaf(qq, kk5, acc[i][5]);
                acc[i][6] = fmaf(qq, kk6, acc[i][6]);
                acc[i][7] = fmaf(qq, kk7, acc[i][7]);
            }
        }
    }

    float ego = ego_table[g_egoidx[b] * NHEAD + head];
#pragma unroll
    for (int i = 0; i < 4; i++) {
        int n = tr + 16 * i;
        int ny = n >> 3, nx = n & 7;
#pragma unroll
        for (int mj = 0; mj < 8; mj++) {
            int m = tc * 8 + mj;
            int my = m >> 3, mx = m & 7;
            int ridx = (ny - my + 7) * 15 + (nx - mx + 7);
            sS[n][m] = acc[i][mj] + srel[ridx] + ego;
        }
    }
    __syncthreads();

    // softmax mixing: ws0*softmax(S) + ws1*relu(S)^2
    float w0 = wvec[0], w1 = wvec[1];
    float mw = fmaxf(w0, w1);
    float e0w = __expf(w0 - mw), e1w = __expf(w1 - mw);
    float inv_w = 1.0f / (e0w + e1w);
    float ws0 = e0w * inv_w, ws1 = e1w * inv_w;

    int warp = tid >> 5, lane = tid & 31;
    for (int r = warp * 16; r < warp * 16 + 16; r++) {
        float v0 = sS[r][lane], v1 = sS[r][lane + 32];
        float mx = fmaxf(v0, v1);
#pragma unroll
        for (int off = 16; off > 0; off >>= 1)
            mx = fmaxf(mx, __shfl_xor_sync(0xffffffffu, mx, off));
        float p0 = __expf(v0 - mx), p1 = __expf(v1 - mx);
        float s = p0 + p1;
#pragma unroll
        for (int off = 16; off > 0; off >>= 1)
            s += __shfl_xor_sync(0xffffffffu, s, off);
        float inv = 1.0f / s;
        float r0 = fmaxf(v0, 0.0f), r1 = fmaxf(v1, 0.0f);
        sS[r][lane]      = ws0 * p0 * inv + ws1 * r0 * r0;
        sS[r][lane + 32] = ws0 * p1 * inv + ws1 * r1 * r1;
    }
    __syncthreads();

    // O = P @ V : thread -> rows {tr+16i}, cols tc*4..tc*4+3
    float o[4][4];
#pragma unroll
    for (int i = 0; i < 4; i++)
#pragma unroll
        for (int j = 0; j < 4; j++) o[i][j] = 0.0f;

#pragma unroll
    for (int m4 = 0; m4 < 16; m4++) {
        float4 vv[4];
#pragma unroll
        for (int jm = 0; jm < 4; jm++) vv[jm] = *(float4*)&sv[m4 * 4 + jm][tc * 4];
        float4 pv[4];
#pragma unroll
        for (int i = 0; i < 4; i++) pv[i] = *(float4*)&sS[tr + 16 * i][m4 * 4];
#pragma unroll
        for (int i = 0; i < 4; i++) {
#pragma unroll
            for (int jm = 0; jm < 4; jm++) {
                float p = (jm == 0) ? pv[i].x : (jm == 1) ? pv[i].y : (jm == 2) ? pv[i].z : pv[i].w;
                o[i][0] = fmaf(p, vv[jm].x, o[i][0]);
                o[i][1] = fmaf(p, vv[jm].y, o[i][1]);
                o[i][2] = fmaf(p, vv[jm].z, o[i][2]);
                o[i][3] = fmaf(p, vv[jm].w, o[i][3]);
            }
        }
    }

#pragma unroll
    for (int i = 0; i < 4; i++) {
        int n = tr + 16 * i;
        float4 r4; r4.x = o[i][0]; r4.y = o[i][1]; r4.z = o[i][2]; r4.w = o[i][3];
        *(float4*)(g_ao + (size_t)(b * NTOK + n) * CH + head * HD + tc * 4) = r4;
    }
}

// ---------------- launch ----------------
extern "C" void kernel_launch(void* const* d_in, const int* in_sizes, int n_in,
                              void* d_out, int out_size) {
    const float* x    = (const float*)d_in[0];
    const float* aff  = (const float*)d_in[1];
    const float* Wq   = (const float*)d_in[2];
    const float* bq   = (const float*)d_in[3];
    const float* Wkv  = (const float*)d_in[4];
    const float* bkv  = (const float*)d_in[5];
    const float* Wp   = (const float*)d_in[6];
    const float* bp   = (const float*)d_in[7];
    const float* rel  = (const float*)d_in[8];
    const float* ego  = (const float*)d_in[9];
    const float* w    = (const float*)d_in[10];
    float* out = (float*)d_out;

    pack_kernel<<<768, 256>>>(Wq, bq, Wkv, bkv);
    ego_kernel<<<1, 256>>>(aff);
    gemm_tf32<<<dim3(6, 1024), 256>>>(x, nullptr, nullptr, 768, 0, nullptr);
    attn_kernel<<<BWIN * NHEAD, 128>>>(rel, ego, w);
    gemm_tf32<<<dim3(2, 1024), 256>>>(nullptr, Wp, bp, 256, 1, out);
}

// round 2
// speedup vs baseline: 1.7511x; 1.7511x over previous
#include <cuda_runtime.h>
#include <cstdint>
#include <cstddef>

// ---------------- problem constants ----------------
#define NCAV     2
#define WIN      8
#define NWY      32
#define NWX      32
#define BWIN     2048
#define NTOK     64
#define CH       256
#define NHEAD    8
#define HD       32
#define MROWS    (BWIN*NTOK)    // 131072
#define SCALE_Q  0.17677669529663687f
#define PI_F     3.14159274101257324f

// ---------------- scratch ----------------
__device__ float g_q [BWIN*NHEAD*NTOK*HD];
__device__ float g_k [BWIN*NHEAD*NTOK*HD];
__device__ float g_v [BWIN*NHEAD*NTOK*HD];
__device__ float g_ao[(size_t)MROWS*CH];     // rounded x, then attn output
__device__ float g_wqkv[CH*768];
__device__ float g_wp[CH*CH];
__device__ float g_bqkv[768];
__device__ int   g_egoidx[BWIN];

// ---------------- helpers ----------------
__device__ __forceinline__ float rndtf(float f) {
    uint32_t r;
    asm("cvt.rna.tf32.f32 %0, %1;\n" : "=r"(r) : "f"(f));
    return __uint_as_float(r);
}

__device__ __forceinline__ void mma_tf32(float c[4], const uint32_t a[4], const uint32_t b[2]) {
    asm volatile(
        "mma.sync.aligned.m16n8k8.row.col.f32.tf32.tf32.f32 "
        "{%0,%1,%2,%3},{%4,%5,%6,%7},{%8,%9},{%0,%1,%2,%3};\n"
        : "+f"(c[0]), "+f"(c[1]), "+f"(c[2]), "+f"(c[3])
        : "r"(a[0]), "r"(a[1]), "r"(a[2]), "r"(a[3]), "r"(b[0]), "r"(b[1]));
}

__device__ __forceinline__ void cpasync16(void* s, const void* g) {
    uint32_t sa = (uint32_t)__cvta_generic_to_shared(s);
    asm volatile("cp.async.cg.shared.global [%0], [%1], 16;\n" :: "r"(sa), "l"(g));
}

// ---------------- kernel 1: pack + pre-round weights ----------------
__global__ void pack_kernel(const float* __restrict__ Wq, const float* __restrict__ bq,
                            const float* __restrict__ Wkv, const float* __restrict__ bkv,
                            const float* __restrict__ Wp) {
    int t = blockIdx.x * blockDim.x + threadIdx.x;  // 196608
    int k = t / 768, j = t % 768;
    g_wqkv[t] = rndtf((j < CH) ? Wq[k*CH + j] : Wkv[k*512 + (j - CH)]);
    if (t < 768) g_bqkv[t] = (t < CH) ? bq[t] : bkv[t - CH];
    if (t < CH*CH) g_wp[t] = rndtf(Wp[t]);
}

// ---------------- kernel 2: pre-round x into g_ao ----------------
__global__ void prep_x(const float* __restrict__ x) {
    size_t i = ((size_t)blockIdx.x * 256 + threadIdx.x) * 4;
    float4 v = *(const float4*)(x + i);
    v.x = rndtf(v.x); v.y = rndtf(v.y); v.z = rndtf(v.z); v.w = rndtf(v.w);
    *(float4*)(g_ao + i) = v;
}

// ---------------- kernel 3: ego bias bin index ----------------
__global__ void ego_kernel(const float* __restrict__ A) {
    __shared__ float rx[BWIN], ry[BWIN];
    __shared__ float red[256];
    int tid = threadIdx.x;
    float ex[NCAV], ey[NCAV];
#pragma unroll
    for (int c = 0; c < NCAV; c++) {
        ex[c] = A[c*6 + 0] * 128.0f + A[c*6 + 1] * 128.0f + A[c*6 + 2];
        ey[c] = A[c*6 + 3] * 128.0f + A[c*6 + 4] * 128.0f + A[c*6 + 5];
    }
    float lmax = 0.0f;
    for (int i = tid; i < BWIN; i += 256) {
        int cav = i >> 10, wi = i & 1023;
        int gy = wi >> 5, gx = wi & 31;
        float cx = gx * (float)WIN + WIN * 0.5f;
        float cy = gy * (float)WIN + WIN * 0.5f;
        float rxx = cx - ex[cav], ryy = cy - ey[cav];
        rx[i] = rxx; ry[i] = ryy;
        lmax = fmaxf(lmax, sqrtf(rxx*rxx + ryy*ryy));
    }
    red[tid] = lmax;
    __syncthreads();
    for (int s = 128; s > 0; s >>= 1) {
        if (tid < s) red[tid] = fmaxf(red[tid], red[tid + s]);
        __syncthreads();
    }
    float maxd = red[0] + 1e-6f;
    for (int i = tid; i < BWIN; i += 256) {
        float rxx = rx[i], ryy = ry[i];
        float d = sqrtf(rxx*rxx + ryy*ryy);
        int db = (int)(d / maxd * 3.0f);
        float ang = atan2f(ryy, rxx);
        int ab = (int)((ang + PI_F) / (2.0f * PI_F) * 3.0f);
        g_egoidx[i] = db * 4 + ab;
    }
}

// ---------------- GEMM: cp.async double-buffered TF32 ----------------
// C[M,N] = A[M,256] @ B[256,N] + bias.  A = g_ao (pre-rounded).
// mode 0: B = g_wqkv (ldb 768), scatter epilogue into q/k/v (rounded, q scaled)
// mode 1: B = g_wp   (ldb 256), write d_out
#define GEMM_ISSUE(st, k0) do {                                               \
    _Pragma("unroll")                                                         \
    for (int ii = 0; ii < 4; ii++) {                                          \
        int c = tid + ii * 256;                                               \
        if (c < 512) { int row = c >> 2, kc = (c & 3) * 4;                    \
            cpasync16(&As[st][row][kc], Ap + (size_t)(bm0 + row) * 256 + (k0) + kc); } \
        else { int c2 = c - 512, kr = c2 >> 5, nc = (c2 & 31) * 4;            \
            cpasync16(&Bs[st][kr][nc], Bp + (size_t)((k0) + kr) * ldb + bn0 + nc); }  \
    }                                                                         \
    asm volatile("cp.async.commit_group;\n");                                 \
} while (0)

__global__ __launch_bounds__(256) void gemm_tf32(
    const float* __restrict__ bias_ext, int ldb, int mode, float* __restrict__ out)
{
    const float* __restrict__ Ap    = g_ao;
    const float* __restrict__ Bp    = (mode == 0) ? g_wqkv : g_wp;
    const float* __restrict__ biasp = (mode == 0) ? g_bqkv : bias_ext;

    __shared__ float As[2][128][20];
    __shared__ float Bs[2][16][136];

    const int bm0 = blockIdx.y * 128;
    const int bn0 = blockIdx.x * 128;
    int tid = threadIdx.x, warp = tid >> 5, lane = tid & 31;
    int wm = (warp & 1) * 64, wn = (warp >> 1) * 32;
    int gid = lane >> 2, tig = lane & 3;

    float acc[4][4][4];
#pragma unroll
    for (int i = 0; i < 4; i++)
#pragma unroll
        for (int j = 0; j < 4; j++)
#pragma unroll
            for (int e = 0; e < 4; e++) acc[i][j][e] = 0.0f;

    GEMM_ISSUE(0, 0);

    for (int kt = 0; kt < 16; kt++) {
        int st = kt & 1;
        if (kt < 15) {
            GEMM_ISSUE(st ^ 1, (kt + 1) * 16);
            asm volatile("cp.async.wait_group 1;\n");
        } else {
            asm volatile("cp.async.wait_group 0;\n");
        }
        __syncthreads();
#pragma unroll
        for (int ks = 0; ks < 16; ks += 8) {
            uint32_t af[4][4], bf[4][2];
#pragma unroll
            for (int mt = 0; mt < 4; mt++) {
                int m = wm + mt * 16 + gid;
                af[mt][0] = __float_as_uint(As[st][m    ][ks + tig]);
                af[mt][1] = __float_as_uint(As[st][m + 8][ks + tig]);
                af[mt][2] = __float_as_uint(As[st][m    ][ks + tig + 4]);
                af[mt][3] = __float_as_uint(As[st][m + 8][ks + tig + 4]);
            }
#pragma unroll
            for (int nt = 0; nt < 4; nt++) {
                int n = wn + nt * 8 + gid;
                bf[nt][0] = __float_as_uint(Bs[st][ks + tig    ][n]);
                bf[nt][1] = __float_as_uint(Bs[st][ks + tig + 4][n]);
            }
#pragma unroll
            for (int mt = 0; mt < 4; mt++)
#pragma unroll
                for (int nt = 0; nt < 4; nt++)
                    mma_tf32(acc[mt][nt], af[mt], bf[nt]);
        }
        __syncthreads();
    }

    // epilogue
#pragma unroll
    for (int mt = 0; mt < 4; mt++) {
#pragma unroll
        for (int nt = 0; nt < 4; nt++) {
            int n = bn0 + wn + nt * 8 + 2 * tig;
            float b0 = biasp[n], b1 = biasp[n + 1];
#pragma unroll
            for (int half = 0; half < 2; half++) {
                int m = bm0 + wm + mt * 16 + gid + half * 8;
                float v0 = acc[mt][nt][half * 2]     + b0;
                float v1 = acc[mt][nt][half * 2 + 1] + b1;
                if (mode == 0) {
                    int part = n >> 8, cc = n & 255;
                    int head = cc >> 5, d = cc & 31;
                    int b = m >> 6, tok = m & 63;
                    if (part == 0) { v0 *= SCALE_Q; v1 *= SCALE_Q; }
                    float* dst = (part == 0) ? g_q : ((part == 1) ? g_k : g_v);
                    float2 r2; r2.x = rndtf(v0); r2.y = rndtf(v1);
                    *(float2*)&dst[(((size_t)(b * NHEAD + head)) * NTOK + tok) * HD + d] = r2;
                } else {
                    float2 r2; r2.x = v0; r2.y = v1;
                    *(float2*)&out[(size_t)m * CH + n] = r2;
                }
            }
        }
    }
}

// ---------------- kernel: tensor-core attention ----------------
// block = (window, head); 4 warps; warp w owns rows wm..wm+15
__global__ __launch_bounds__(128) void attn_kernel(
    const float* __restrict__ rel_table, const float* __restrict__ ego_table,
    const float* __restrict__ wvec)
{
    __shared__ float sk[NTOK][40];   // K row-major [m][d], pad 40 -> conflict-free frags
    __shared__ float sv[NTOK][40];   // V row-major [m][d]
    __shared__ float sP[NTOK][68];   // mixed attention probs (tf32-rounded)
    __shared__ float srel[225];

    int bh = blockIdx.x;
    int b = bh >> 3, head = bh & 7;
    int tid = threadIdx.x, warp = tid >> 5, lane = tid & 31;
    int gid = lane >> 2, tig = lane & 3;
    int wm = warp * 16;
    size_t base = (size_t)bh * (NTOK * HD);

    int n0 = wm + gid, n1 = wm + gid + 8;

    // q fragments straight from gmem (rows are warp-private)
    uint32_t qf[4][4];
    const float* qp = g_q + base;
#pragma unroll
    for (int ksi = 0; ksi < 4; ksi++) {
        qf[ksi][0] = __float_as_uint(qp[n0 * HD + ksi * 8 + tig]);
        qf[ksi][1] = __float_as_uint(qp[n1 * HD + ksi * 8 + tig]);
        qf[ksi][2] = __float_as_uint(qp[n0 * HD + ksi * 8 + tig + 4]);
        qf[ksi][3] = __float_as_uint(qp[n1 * HD + ksi * 8 + tig + 4]);
    }

    // K/V tiles
#pragma unroll
    for (int i = 0; i < 4; i++) {
        int v = tid + i * 128;
        int row = v >> 3, c4 = v & 7;
        *(float4*)&sk[row][c4 * 4] = *(const float4*)(g_k + base + row * HD + c4 * 4);
        *(float4*)&sv[row][c4 * 4] = *(const float4*)(g_v + base + row * HD + c4 * 4);
    }
    for (int i = tid; i < 225; i += 128) srel[i] = rel_table[i * NHEAD + head];
    __syncthreads();

    // ---- S = q @ k^T : warp computes rows [wm, wm+16) x all 64 cols ----
    float sacc[8][4];
#pragma unroll
    for (int nt = 0; nt < 8; nt++)
#pragma unroll
        for (int e = 0; e < 4; e++) sacc[nt][e] = 0.0f;

#pragma unroll
    for (int ksi = 0; ksi < 4; ksi++) {
        uint32_t bf[8][2];
#pragma unroll
        for (int nt = 0; nt < 8; nt++) {
            bf[nt][0] = __float_as_uint(sk[nt * 8 + gid][ksi * 8 + tig]);
            bf[nt][1] = __float_as_uint(sk[nt * 8 + gid][ksi * 8 + tig + 4]);
        }
#pragma unroll
        for (int nt = 0; nt < 8; nt++) mma_tf32(sacc[nt], qf[ksi], bf[nt]);
    }

    // biases
    float ego_b = ego_table[g_egoidx[b] * NHEAD + head];
    int ny0 = n0 >> 3, nx0 = n0 & 7, ny1 = n1 >> 3, nx1 = n1 & 7;
#pragma unroll
    for (int nt = 0; nt < 8; nt++) {
#pragma unroll
        for (int e = 0; e < 4; e++) {
            int m = nt * 8 + 2 * tig + (e & 1);
            int my = m >> 3, mx = m & 7;
            int ny = (e < 2) ? ny0 : ny1, nx = (e < 2) ? nx0 : nx1;
            sacc[nt][e] += srel[(ny - my + 7) * 15 + (nx - mx + 7)] + ego_b;
        }
    }

    // mixing weights
    float w0 = wvec[0], w1 = wvec[1];
    float mw = fmaxf(w0, w1);
    float e0w = __expf(w0 - mw), e1w = __expf(w1 - mw);
    float inv_w = 1.0f / (e0w + e1w);
    float ws0 = e0w * inv_w, ws1 = e1w * inv_w;

    // ---- register softmax: row lives in a quad (shfl_xor 1,2) ----
    float mx0 = -1e30f, mx1 = -1e30f;
#pragma unroll
    for (int nt = 0; nt < 8; nt++) {
        mx0 = fmaxf(mx0, fmaxf(sacc[nt][0], sacc[nt][1]));
        mx1 = fmaxf(mx1, fmaxf(sacc[nt][2], sacc[nt][3]));
    }
    mx0 = fmaxf(mx0, __shfl_xor_sync(0xffffffffu, mx0, 1));
    mx0 = fmaxf(mx0, __shfl_xor_sync(0xffffffffu, mx0, 2));
    mx1 = fmaxf(mx1, __shfl_xor_sync(0xffffffffu, mx1, 1));
    mx1 = fmaxf(mx1, __shfl_xor_sync(0xffffffffu, mx1, 2));

    float p[8][4];
    float sum0 = 0.0f, sum1 = 0.0f;
#pragma unroll
    for (int nt = 0; nt < 8; nt++) {
        p[nt][0] = __expf(sacc[nt][0] - mx0); sum0 += p[nt][0];
        p[nt][1] = __expf(sacc[nt][1] - mx0); sum0 += p[nt][1];
        p[nt][2] = __expf(sacc[nt][2] - mx1); sum1 += p[nt][2];
        p[nt][3] = __expf(sacc[nt][3] - mx1); sum1 += p[nt][3];
    }
    sum0 += __shfl_xor_sync(0xffffffffu, sum0, 1);
    sum0 += __shfl_xor_sync(0xffffffffu, sum0, 2);
    sum1 += __shfl_xor_sync(0xffffffffu, sum1, 1);
    sum1 += __shfl_xor_sync(0xffffffffu, sum1, 2);
    float inv0 = 1.0f / sum0, inv1 = 1.0f / sum1;

#pragma unroll
    for (int nt = 0; nt < 8; nt++) {
        float r0a = fmaxf(sacc[nt][0], 0.0f), r0b = fmaxf(sacc[nt][1], 0.0f);
        float r1a = fmaxf(sacc[nt][2], 0.0f), r1b = fmaxf(sacc[nt][3], 0.0f);
        float2 P0, P1;
        P0.x = rndtf(ws0 * p[nt][0] * inv0 + ws1 * r0a * r0a);
        P0.y = rndtf(ws0 * p[nt][1] * inv0 + ws1 * r0b * r0b);
        P1.x = rndtf(ws0 * p[nt][2] * inv1 + ws1 * r1a * r1a);
        P1.y = rndtf(ws0 * p[nt][3] * inv1 + ws1 * r1b * r1b);
        *(float2*)&sP[n0][nt * 8 + 2 * tig] = P0;
        *(float2*)&sP[n1][nt * 8 + 2 * tig] = P1;
    }
    __syncwarp();

    // ---- O = P @ V : rows wm..wm+15 x 32 dims ----
    float oacc[4][4];
#pragma unroll
    for (int nt = 0; nt < 4; nt++)
#pragma unroll
        for (int e = 0; e < 4; e++) oacc[nt][e] = 0.0f;

#pragma unroll
    for (int ksi = 0; ksi < 8; ksi++) {
        uint32_t pf[4];
        pf[0] = __float_as_uint(sP[n0][ksi * 8 + tig]);
        pf[1] = __float_as_uint(sP[n1][ksi * 8 + tig]);
        pf[2] = __float_as_uint(sP[n0][ksi * 8 + tig + 4]);
        pf[3] = __float_as_uint(sP[n1][ksi * 8 + tig + 4]);
        uint32_t vf[4][2];
#pragma unroll
        for (int nt = 0; nt < 4; nt++) {
            vf[nt][0] = __float_as_uint(sv[ksi * 8 + tig    ][nt * 8 + gid]);
            vf[nt][1] = __float_as_uint(sv[ksi * 8 + tig + 4][nt * 8 + gid]);
        }
#pragma unroll
        for (int nt = 0; nt < 4; nt++) mma_tf32(oacc[nt], pf, vf[nt]);
    }

    // store (rounded: feeds the mode-1 GEMM's mma directly)
    float* aop = g_ao + (size_t)(b * NTOK) * CH + head * HD;
#pragma unroll
    for (int nt = 0; nt < 4; nt++) {
        int d0 = nt * 8 + 2 * tig;
        float2 s0, s1;
        s0.x = rndtf(oacc[nt][0]); s0.y = rndtf(oacc[nt][1]);
        s1.x = rndtf(oacc[nt][2]); s1.y = rndtf(oacc[nt][3]);
        *(float2*)(aop + (size_t)n0 * CH + d0) = s0;
        *(float2*)(aop + (size_t)n1 * CH + d0) = s1;
    }
}

// ---------------- launch ----------------
extern "C" void kernel_launch(void* const* d_in, const int* in_sizes, int n_in,
                              void* d_out, int out_size) {
    const float* x    = (const float*)d_in[0];
    const float* aff  = (const float*)d_in[1];
    const float* Wq   = (const float*)d_in[2];
    const float* bq   = (const float*)d_in[3];
    const float* Wkv  = (const float*)d_in[4];
    const float* bkv  = (const float*)d_in[5];
    const float* Wp   = (const float*)d_in[6];
    const float* bp   = (const float*)d_in[7];
    const float* rel  = (const float*)d_in[8];
    const float* ego  = (const float*)d_in[9];
    const float* w    = (const float*)d_in[10];
    float* out = (float*)d_out;

    pack_kernel<<<768, 256>>>(Wq, bq, Wkv, bkv, Wp);
    ego_kernel<<<1, 256>>>(aff);
    prep_x<<<32768, 256>>>(x);
    gemm_tf32<<<dim3(6, 1024), 256>>>(nullptr, 768, 0, nullptr);
    attn_kernel<<<BWIN * NHEAD, 128>>>(rel, ego, w);
    gemm_tf32<<<dim3(2, 1024), 256>>>(bp, 256, 1, out);
}

// round 3
// speedup vs baseline: 1.7619x; 1.0061x over previous
#include <cuda_runtime.h>
#include <cstdint>
#include <cstddef>

// ---------------- problem constants ----------------
#define NCAV     2
#define WIN      8
#define NWY      32
#define NWX      32
#define BWIN     2048
#define NTOK     64
#define CH       256
#define NHEAD    8
#define HD       32
#define MROWS    (BWIN*NTOK)    // 131072
#define SCALE_Q  0.17677669529663687f
#define PI_F     3.14159274101257324f

// ---------------- scratch ----------------
__device__ float g_q [BWIN*NHEAD*NTOK*HD];
__device__ float g_k [BWIN*NHEAD*NTOK*HD];
__device__ float g_v [BWIN*NHEAD*NTOK*HD];
__device__ float g_ao[(size_t)MROWS*CH];     // rounded x, then attn output
__device__ float g_wqkv[CH*768];
__device__ float g_wp[CH*CH];
__device__ float g_bqkv[768];
__device__ int   g_egoidx[BWIN];

// ---------------- helpers ----------------
__device__ __forceinline__ float rndtf(float f) {
    uint32_t r;
    asm("cvt.rna.tf32.f32 %0, %1;\n" : "=r"(r) : "f"(f));
    return __uint_as_float(r);
}

__device__ __forceinline__ void mma_tf32(float c[4], const uint32_t a[4], const uint32_t b[2]) {
    asm volatile(
        "mma.sync.aligned.m16n8k8.row.col.f32.tf32.tf32.f32 "
        "{%0,%1,%2,%3},{%4,%5,%6,%7},{%8,%9},{%0,%1,%2,%3};\n"
        : "+f"(c[0]), "+f"(c[1]), "+f"(c[2]), "+f"(c[3])
        : "r"(a[0]), "r"(a[1]), "r"(a[2]), "r"(a[3]), "r"(b[0]), "r"(b[1]));
}

__device__ __forceinline__ void cpasync16(void* s, const void* g) {
    uint32_t sa = (uint32_t)__cvta_generic_to_shared(s);
    asm volatile("cp.async.cg.shared.global [%0], [%1], 16;\n" :: "r"(sa), "l"(g));
}

// ---------------- kernel 1: pack + pre-round weights ----------------
__global__ void pack_kernel(const float* __restrict__ Wq, const float* __restrict__ bq,
                            const float* __restrict__ Wkv, const float* __restrict__ bkv,
                            const float* __restrict__ Wp) {
    int t = blockIdx.x * blockDim.x + threadIdx.x;  // 196608
    int k = t / 768, j = t % 768;
    g_wqkv[t] = rndtf((j < CH) ? Wq[k*CH + j] : Wkv[k*512 + (j - CH)]);
    if (t < 768) g_bqkv[t] = (t < CH) ? bq[t] : bkv[t - CH];
    if (t < CH*CH) g_wp[t] = rndtf(Wp[t]);
}

// ---------------- kernel 2: pre-round x into g_ao ----------------
__global__ void prep_x(const float* __restrict__ x) {
    size_t i = ((size_t)blockIdx.x * 256 + threadIdx.x) * 4;
    float4 v = *(const float4*)(x + i);
    v.x = rndtf(v.x); v.y = rndtf(v.y); v.z = rndtf(v.z); v.w = rndtf(v.w);
    *(float4*)(g_ao + i) = v;
}

// ---------------- kernel 3: ego bias bin index ----------------
__global__ void ego_kernel(const float* __restrict__ A) {
    __shared__ float rx[BWIN], ry[BWIN];
    __shared__ float red[256];
    int tid = threadIdx.x;
    float ex[NCAV], ey[NCAV];
#pragma unroll
    for (int c = 0; c < NCAV; c++) {
        ex[c] = A[c*6 + 0] * 128.0f + A[c*6 + 1] * 128.0f + A[c*6 + 2];
        ey[c] = A[c*6 + 3] * 128.0f + A[c*6 + 4] * 128.0f + A[c*6 + 5];
    }
    float lmax = 0.0f;
    for (int i = tid; i < BWIN; i += 256) {
        int cav = i >> 10, wi = i & 1023;
        int gy = wi >> 5, gx = wi & 31;
        float cx = gx * (float)WIN + WIN * 0.5f;
        float cy = gy * (float)WIN + WIN * 0.5f;
        float rxx = cx - ex[cav], ryy = cy - ey[cav];
        rx[i] = rxx; ry[i] = ryy;
        lmax = fmaxf(lmax, sqrtf(rxx*rxx + ryy*ryy));
    }
    red[tid] = lmax;
    __syncthreads();
    for (int s = 128; s > 0; s >>= 1) {
        if (tid < s) red[tid] = fmaxf(red[tid], red[tid + s]);
        __syncthreads();
    }
    float maxd = red[0] + 1e-6f;
    for (int i = tid; i < BWIN; i += 256) {
        float rxx = rx[i], ryy = ry[i];
        float d = sqrtf(rxx*rxx + ryy*ryy);
        int db = (int)(d / maxd * 3.0f);
        float ang = atan2f(ryy, rxx);
        int ab = (int)((ang + PI_F) / (2.0f * PI_F) * 3.0f);
        g_egoidx[i] = db * 4 + ab;
    }
}

// ---------------- GEMM: cp.async double-buffered TF32 ----------------
// C[M,N] = A[M,256] @ B[256,N] + bias.  A = g_ao (pre-rounded).
// mode 0: B = g_wqkv (ldb 768), scatter epilogue into q/k/v (rounded, q scaled)
// mode 1: B = g_wp   (ldb 256), write d_out
#define GEMM_ISSUE(st, k0) do {                                               \
    _Pragma("unroll")                                                         \
    for (int ii = 0; ii < 4; ii++) {                                          \
        int c = tid + ii * 256;                                               \
        if (c < 512) { int row = c >> 2, kc = (c & 3) * 4;                    \
            cpasync16(&As[st][row][kc], Ap + (size_t)(bm0 + row) * 256 + (k0) + kc); } \
        else { int c2 = c - 512, kr = c2 >> 5, nc = (c2 & 31) * 4;            \
            cpasync16(&Bs[st][kr][nc], Bp + (size_t)((k0) + kr) * ldb + bn0 + nc); }  \
    }                                                                         \
    asm volatile("cp.async.commit_group;\n");                                 \
} while (0)

__global__ __launch_bounds__(256) void gemm_tf32(
    const float* __restrict__ bias_ext, int ldb, int mode, float* __restrict__ out)
{
    const float* __restrict__ Ap    = g_ao;
    const float* __restrict__ Bp    = (mode == 0) ? g_wqkv : g_wp;
    const float* __restrict__ biasp = (mode == 0) ? g_bqkv : bias_ext;

    __shared__ float As[2][128][20];
    __shared__ float Bs[2][16][136];

    const int bm0 = blockIdx.y * 128;
    const int bn0 = blockIdx.x * 128;
    int tid = threadIdx.x, warp = tid >> 5, lane = tid & 31;
    int wm = (warp & 1) * 64, wn = (warp >> 1) * 32;
    int gid = lane >> 2, tig = lane & 3;

    float acc[4][4][4];
#pragma unroll
    for (int i = 0; i < 4; i++)
#pragma unroll
        for (int j = 0; j < 4; j++)
#pragma unroll
            for (int e = 0; e < 4; e++) acc[i][j][e] = 0.0f;

    GEMM_ISSUE(0, 0);

    for (int kt = 0; kt < 16; kt++) {
        int st = kt & 1;
        if (kt < 15) {
            GEMM_ISSUE(st ^ 1, (kt + 1) * 16);
            asm volatile("cp.async.wait_group 1;\n");
        } else {
            asm volatile("cp.async.wait_group 0;\n");
        }
        __syncthreads();
#pragma unroll
        for (int ks = 0; ks < 16; ks += 8) {
            uint32_t af[4][4], bf[4][2];
#pragma unroll
            for (int mt = 0; mt < 4; mt++) {
                int m = wm + mt * 16 + gid;
                af[mt][0] = __float_as_uint(As[st][m    ][ks + tig]);
                af[mt][1] = __float_as_uint(As[st][m + 8][ks + tig]);
                af[mt][2] = __float_as_uint(As[st][m    ][ks + tig + 4]);
                af[mt][3] = __float_as_uint(As[st][m + 8][ks + tig + 4]);
            }
#pragma unroll
            for (int nt = 0; nt < 4; nt++) {
                int n = wn + nt * 8 + gid;
                bf[nt][0] = __float_as_uint(Bs[st][ks + tig    ][n]);
                bf[nt][1] = __float_as_uint(Bs[st][ks + tig + 4][n]);
            }
#pragma unroll
            for (int mt = 0; mt < 4; mt++)
#pragma unroll
                for (int nt = 0; nt < 4; nt++)
                    mma_tf32(acc[mt][nt], af[mt], bf[nt]);
        }
        __syncthreads();
    }

    // epilogue
#pragma unroll
    for (int mt = 0; mt < 4; mt++) {
#pragma unroll
        for (int nt = 0; nt < 4; nt++) {
            int n = bn0 + wn + nt * 8 + 2 * tig;
            float b0 = biasp[n], b1 = biasp[n + 1];
#pragma unroll
            for (int half = 0; half < 2; half++) {
                int m = bm0 + wm + mt * 16 + gid + half * 8;
                float v0 = acc[mt][nt][half * 2]     + b0;
                float v1 = acc[mt][nt][half * 2 + 1] + b1;
                if (mode == 0) {
                    int part = n >> 8, cc = n & 255;
                    int head = cc >> 5, d = cc & 31;
                    int b = m >> 6, tok = m & 63;
                    if (part == 0) { v0 *= SCALE_Q; v1 *= SCALE_Q; }
                    float* dst = (part == 0) ? g_q : ((part == 1) ? g_k : g_v);
                    float2 r2; r2.x = rndtf(v0); r2.y = rndtf(v1);
                    *(float2*)&dst[(((size_t)(b * NHEAD + head)) * NTOK + tok) * HD + d] = r2;
                } else {
                    float2 r2; r2.x = v0; r2.y = v1;
                    *(float2*)&out[(size_t)m * CH + n] = r2;
                }
            }
        }
    }
}

// ---------------- kernel: tensor-core attention ----------------
// block = (window, head); 4 warps; warp w owns rows wm..wm+15
__global__ __launch_bounds__(128) void attn_kernel(
    const float* __restrict__ rel_table, const float* __restrict__ ego_table,
    const float* __restrict__ wvec)
{
    __shared__ float sk[NTOK][40];   // K row-major [m][d], pad 40 -> conflict-free frags
    __shared__ float sv[NTOK][40];   // V row-major [m][d]
    __shared__ float sP[NTOK][68];   // mixed attention probs (tf32-rounded)
    __shared__ float srel[225];

    int bh = blockIdx.x;
    int b = bh >> 3, head = bh & 7;
    int tid = threadIdx.x, warp = tid >> 5, lane = tid & 31;
    int gid = lane >> 2, tig = lane & 3;
    int wm = warp * 16;
    size_t base = (size_t)bh * (NTOK * HD);

    int n0 = wm + gid, n1 = wm + gid + 8;

    // q fragments straight from gmem (rows are warp-private)
    uint32_t qf[4][4];
    const float* qp = g_q + base;
#pragma unroll
    for (int ksi = 0; ksi < 4; ksi++) {
        qf[ksi][0] = __float_as_uint(qp[n0 * HD + ksi * 8 + tig]);
        qf[ksi][1] = __float_as_uint(qp[n1 * HD + ksi * 8 + tig]);
        qf[ksi][2] = __float_as_uint(qp[n0 * HD + ksi * 8 + tig + 4]);
        qf[ksi][3] = __float_as_uint(qp[n1 * HD + ksi * 8 + tig + 4]);
    }

    // K/V tiles
#pragma unroll
    for (int i = 0; i < 4; i++) {
        int v = tid + i * 128;
        int row = v >> 3, c4 = v & 7;
        *(float4*)&sk[row][c4 * 4] = *(const float4*)(g_k + base + row * HD + c4 * 4);
        *(float4*)&sv[row][c4 * 4] = *(const float4*)(g_v + base + row * HD + c4 * 4);
    }
    for (int i = tid; i < 225; i += 128) srel[i] = rel_table[i * NHEAD + head];
    __syncthreads();

    // ---- S = q @ k^T : warp computes rows [wm, wm+16) x all 64 cols ----
    float sacc[8][4];
#pragma unroll
    for (int nt = 0; nt < 8; nt++)
#pragma unroll
        for (int e = 0; e < 4; e++) sacc[nt][e] = 0.0f;

#pragma unroll
    for (int ksi = 0; ksi < 4; ksi++) {
        uint32_t bf[8][2];
#pragma unroll
        for (int nt = 0; nt < 8; nt++) {
            bf[nt][0] = __float_as_uint(sk[nt * 8 + gid][ksi * 8 + tig]);
            bf[nt][1] = __float_as_uint(sk[nt * 8 + gid][ksi * 8 + tig + 4]);
        }
#pragma unroll
        for (int nt = 0; nt < 8; nt++) mma_tf32(sacc[nt], qf[ksi], bf[nt]);
    }

    // biases
    float ego_b = ego_table[g_egoidx[b] * NHEAD + head];
    int ny0 = n0 >> 3, nx0 = n0 & 7, ny1 = n1 >> 3, nx1 = n1 & 7;
#pragma unroll
    for (int nt = 0; nt < 8; nt++) {
#pragma unroll
        for (int e = 0; e < 4; e++) {
            int m = nt * 8 + 2 * tig + (e & 1);
            int my = m >> 3, mx = m & 7;
            int ny = (e < 2) ? ny0 : ny1, nx = (e < 2) ? nx0 : nx1;
            sacc[nt][e] += srel[(ny - my + 7) * 15 + (nx - mx + 7)] + ego_b;
        }
    }

    // mixing weights
    float w0 = wvec[0], w1 = wvec[1];
    float mw = fmaxf(w0, w1);
    float e0w = __expf(w0 - mw), e1w = __expf(w1 - mw);
    float inv_w = 1.0f / (e0w + e1w);
    float ws0 = e0w * inv_w, ws1 = e1w * inv_w;

    // ---- register softmax: row lives in a quad (shfl_xor 1,2) ----
    float mx0 = -1e30f, mx1 = -1e30f;
#pragma unroll
    for (int nt = 0; nt < 8; nt++) {
        mx0 = fmaxf(mx0, fmaxf(sacc[nt][0], sacc[nt][1]));
        mx1 = fmaxf(mx1, fmaxf(sacc[nt][2], sacc[nt][3]));
    }
    mx0 = fmaxf(mx0, __shfl_xor_sync(0xffffffffu, mx0, 1));
    mx0 = fmaxf(mx0, __shfl_xor_sync(0xffffffffu, mx0, 2));
    mx1 = fmaxf(mx1, __shfl_xor_sync(0xffffffffu, mx1, 1));
    mx1 = fmaxf(mx1, __shfl_xor_sync(0xffffffffu, mx1, 2));

    float p[8][4];
    float sum0 = 0.0f, sum1 = 0.0f;
#pragma unroll
    for (int nt = 0; nt < 8; nt++) {
        p[nt][0] = __expf(sacc[nt][0] - mx0); sum0 += p[nt][0];
        p[nt][1] = __expf(sacc[nt][1] - mx0); sum0 += p[nt][1];
        p[nt][2] = __expf(sacc[nt][2] - mx1); sum1 += p[nt][2];
        p[nt][3] = __expf(sacc[nt][3] - mx1); sum1 += p[nt][3];
    }
    sum0 += __shfl_xor_sync(0xffffffffu, sum0, 1);
    sum0 += __shfl_xor_sync(0xffffffffu, sum0, 2);
    sum1 += __shfl_xor_sync(0xffffffffu, sum1, 1);
    sum1 += __shfl_xor_sync(0xffffffffu, sum1, 2);
    float inv0 = 1.0f / sum0, inv1 = 1.0f / sum1;

#pragma unroll
    for (int nt = 0; nt < 8; nt++) {
        float r0a = fmaxf(sacc[nt][0], 0.0f), r0b = fmaxf(sacc[nt][1], 0.0f);
        float r1a = fmaxf(sacc[nt][2], 0.0f), r1b = fmaxf(sacc[nt][3], 0.0f);
        float2 P0, P1;
        P0.x = rndtf(ws0 * p[nt][0] * inv0 + ws1 * r0a * r0a);
        P0.y = rndtf(ws0 * p[nt][1] * inv0 + ws1 * r0b * r0b);
        P1.x = rndtf(ws0 * p[nt][2] * inv1 + ws1 * r1a * r1a);
        P1.y = rndtf(ws0 * p[nt][3] * inv1 + ws1 * r1b * r1b);
        *(float2*)&sP[n0][nt * 8 + 2 * tig] = P0;
        *(float2*)&sP[n1][nt * 8 + 2 * tig] = P1;
    }
    __syncwarp();

    // ---- O = P @ V : rows wm..wm+15 x 32 dims ----
    float oacc[4][4];
#pragma unroll
    for (int nt = 0; nt < 4; nt++)
#pragma unroll
        for (int e = 0; e < 4; e++) oacc[nt][e] = 0.0f;

#pragma unroll
    for (int ksi = 0; ksi < 8; ksi++) {
        uint32_t pf[4];
        pf[0] = __float_as_uint(sP[n0][ksi * 8 + tig]);
        pf[1] = __float_as_uint(sP[n1][ksi * 8 + tig]);
        pf[2] = __float_as_uint(sP[n0][ksi * 8 + tig + 4]);
        pf[3] = __float_as_uint(sP[n1][ksi * 8 + tig + 4]);
        uint32_t vf[4][2];
#pragma unroll
        for (int nt = 0; nt < 4; nt++) {
            vf[nt][0] = __float_as_uint(sv[ksi * 8 + tig    ][nt * 8 + gid]);
            vf[nt][1] = __float_as_uint(sv[ksi * 8 + tig + 4][nt * 8 + gid]);
        }
#pragma unroll
        for (int nt = 0; nt < 4; nt++) mma_tf32(oacc[nt], pf, vf[nt]);
    }

    // store (rounded: feeds the mode-1 GEMM's mma directly)
    float* aop = g_ao + (size_t)(b * NTOK) * CH + head * HD;
#pragma unroll
    for (int nt = 0; nt < 4; nt++) {
        int d0 = nt * 8 + 2 * tig;
        float2 s0, s1;
        s0.x = rndtf(oacc[nt][0]); s0.y = rndtf(oacc[nt][1]);
        s1.x = rndtf(oacc[nt][2]); s1.y = rndtf(oacc[nt][3]);
        *(float2*)(aop + (size_t)n0 * CH + d0) = s0;
        *(float2*)(aop + (size_t)n1 * CH + d0) = s1;
    }
}

// ---------------- launch ----------------
extern "C" void kernel_launch(void* const* d_in, const int* in_sizes, int n_in,
                              void* d_out, int out_size) {
    const float* x    = (const float*)d_in[0];
    const float* aff  = (const float*)d_in[1];
    const float* Wq   = (const float*)d_in[2];
    const float* bq   = (const float*)d_in[3];
    const float* Wkv  = (const float*)d_in[4];
    const float* bkv  = (const float*)d_in[5];
    const float* Wp   = (const float*)d_in[6];
    const float* bp   = (const float*)d_in[7];
    const float* rel  = (const float*)d_in[8];
    const float* ego  = (const float*)d_in[9];
    const float* w    = (const float*)d_in[10];
    float* out = (float*)d_out;

    pack_kernel<<<768, 256>>>(Wq, bq, Wkv, bkv, Wp);
    ego_kernel<<<1, 256>>>(aff);
    prep_x<<<32768, 256>>>(x);
    gemm_tf32<<<dim3(6, 1024), 256>>>(nullptr, 768, 0, nullptr);
    attn_kernel<<<BWIN * NHEAD, 128>>>(rel, ego, w);
    gemm_tf32<<<dim3(2, 1024), 256>>>(bp, 256, 1, out);
}